// round 8
// baseline (speedup 1.0000x reference)
#include <cuda_runtime.h>

#define BV      32                     // batch
#define BD      352                    // dsts per bucket
#define NBMAX   320                    // ceil(100000/352) = 285 buckets
#define CAP     16384                  // per-bucket capacity (exp ~11228, sd ~106)
#define CURPAD  64                     // cursor stride in ints (256B) -> distinct LTS lines
#define SC      512                    // scan width (>= BD)

// Static scratch.
__device__ float g_xT[(size_t)131072 * BV];          // x transposed (N, B)
__device__ int   g_cursor[NBMAX * CURPAD];           // padded bucket cursors
__device__ int2  g_edges [(size_t)NBMAX * CAP];      // bucketed (src|dlo<<17, val)
__device__ int2  g_sorted[(size_t)NBMAX * CAP];      // dst-sorted (src, val)
__device__ int   g_rowptr[131072];
__device__ int   g_rowcnt[131072];

// ---------------------------------------------------------------------------
__global__ void init_cursor_kernel(int nbuck) {
    int i = blockIdx.x * blockDim.x + threadIdx.x;
    if (i < nbuck) g_cursor[i * CURPAD] = i * CAP;
}

// Transpose x (B, N) -> g_xT (N, B).
__global__ void transpose_x_kernel(const float* __restrict__ x, int N, int B) {
    __shared__ float tile[32][33];
    int n0 = blockIdx.x * 32;
    int tx = threadIdx.x, ty = threadIdx.y;
    int n = n0 + tx;
    if (ty < B && n < N) tile[ty][tx] = x[(size_t)ty * N + n];
    __syncthreads();
    int nw = n0 + ty;
    if (tx < B && nw < N) g_xT[(size_t)nw * BV + tx] = tile[tx][ty];
}

// Scatter edges into dst-range buckets. One global atomic per edge on a
// 256B-padded cursor (spreads across LTS slices).
__global__ void scatter_kernel(const int* __restrict__ idx,
                               const float* __restrict__ vals, int nnz) {
    int i = blockIdx.x * blockDim.x + threadIdx.x;
    if (i >= nnz) return;
    int d   = idx[nnz + i];
    int b   = d / BD;
    int dlo = d - b * BD;
    int pos = atomicAdd(&g_cursor[b * CURPAD], 1);
    g_edges[pos] = make_int2(idx[i] | (dlo << 17), __float_as_int(vals[i]));
}

// Per-bucket counting sort by dlo. Produces g_sorted + rowptr/rowcnt.
__global__ __launch_bounds__(1024) void sort_kernel(int M) {
    __shared__ int hist[BD];
    __shared__ int scan[SC];
    int bkt  = blockIdx.x;
    int tid  = threadIdx.x;
    int base = bkt * CAP;
    int cnt  = g_cursor[bkt * CURPAD] - base;
    int dst0 = bkt * BD;

    for (int t = tid; t < BD; t += 1024) hist[t] = 0;
    __syncthreads();
    for (int i = tid; i < cnt; i += 1024)
        atomicAdd(&hist[g_edges[base + i].x >> 17], 1);
    __syncthreads();

    // exclusive scan over SC=512 (first 512 threads active; all hit barriers)
    int v = 0;
    if (tid < SC) { v = (tid < BD) ? hist[tid] : 0; scan[tid] = v; }
    __syncthreads();
    for (int off = 1; off < SC; off <<= 1) {
        int t = 0;
        if (tid < SC && tid >= off) t = scan[tid - off];
        __syncthreads();
        if (tid < SC) scan[tid] += t;
        __syncthreads();
    }
    if (tid < BD) {
        int excl = scan[tid] - v;
        if (dst0 + tid < M) {
            g_rowptr[dst0 + tid] = base + excl;
            g_rowcnt[dst0 + tid] = hist[tid];
        }
        hist[tid] = excl;                       // reuse as local cursor
    }
    __syncthreads();
    for (int i = tid; i < cnt; i += 1024) {
        int2 r  = g_edges[base + i];
        int dlo = r.x >> 17;
        int pos = atomicAdd(&hist[dlo], 1);
        g_sorted[base + pos] = make_int2(r.x & 0x1FFFF, r.y);
    }
}

// Gather: one warp per dst row; records coalesced + shuffle-broadcast;
// register accumulation; fused transpose + bias output.
__global__ __launch_bounds__(1024, 2) void gather_kernel(
        float* __restrict__ out, const float* __restrict__ bias, int M, int B) {
    __shared__ float tile[32][33];
    int m0 = blockIdx.x * 32;
    int tx = threadIdx.x;                        // lane = batch
    int ty = threadIdx.y;                        // warp = row
    int m  = m0 + ty;

    float s0 = 0.f, s1 = 0.f, s2 = 0.f, s3 = 0.f;
    if (m < M) {
        int p   = g_rowptr[m];
        int cnt = g_rowcnt[m];
        for (int c0 = 0; c0 < cnt; c0 += 32) {
            int i = c0 + tx;
            int2 r = (i < cnt) ? g_sorted[p + i] : make_int2(0, 0);
            int k = min(32, cnt - c0);
            int u = 0;
            #pragma unroll 1
            for (; u + 4 <= k; u += 4) {
                int   sa = __shfl_sync(0xffffffffu, r.x, u + 0);
                int   sb = __shfl_sync(0xffffffffu, r.x, u + 1);
                int   sc = __shfl_sync(0xffffffffu, r.x, u + 2);
                int   sd = __shfl_sync(0xffffffffu, r.x, u + 3);
                float va = __int_as_float(__shfl_sync(0xffffffffu, r.y, u + 0));
                float vb = __int_as_float(__shfl_sync(0xffffffffu, r.y, u + 1));
                float vc = __int_as_float(__shfl_sync(0xffffffffu, r.y, u + 2));
                float vd = __int_as_float(__shfl_sync(0xffffffffu, r.y, u + 3));
                float xa = g_xT[(size_t)sa * BV + tx];
                float xb = g_xT[(size_t)sb * BV + tx];
                float xc = g_xT[(size_t)sc * BV + tx];
                float xd = g_xT[(size_t)sd * BV + tx];
                s0 += va * xa;
                s1 += vb * xb;
                s2 += vc * xc;
                s3 += vd * xd;
            }
            for (; u < k; u++) {
                int   su = __shfl_sync(0xffffffffu, r.x, u);
                float vu = __int_as_float(__shfl_sync(0xffffffffu, r.y, u));
                s0 += vu * g_xT[(size_t)su * BV + tx];
            }
        }
    }
    tile[ty][tx] = (s0 + s1) + (s2 + s3);
    __syncthreads();
    int mo = m0 + tx;
    if (mo < M && ty < B)
        out[(size_t)ty * M + mo] = tile[tx][ty] + __ldg(bias + mo);
}

// ---------------------------------------------------------------------------
extern "C" void kernel_launch(void* const* d_in, const int* in_sizes, int n_in,
                              void* d_out, int out_size) {
    const float* x    = (const float*)d_in[0];   // (B, N, 1)
    const int*   idx  = (const int*)  d_in[1];   // (2, NNZ): row0=src, row1=dst
    const float* vals = (const float*)d_in[2];   // (NNZ,)
    const float* bias = (const float*)d_in[3];   // (M, 1)
    float*       out  = (float*)d_out;           // (B, M, 1)

    int M   = in_sizes[3];
    int NNZ = in_sizes[1] / 2;
    int B   = out_size / M;
    int N   = in_sizes[0] / B;
    int nbuck = (M + BD - 1) / BD;               // 285

    init_cursor_kernel<<<(nbuck + 255) / 256, 256>>>(nbuck);

    {
        dim3 blk(32, 32);
        transpose_x_kernel<<<(N + 31) / 32, blk>>>(x, N, B);
    }

    scatter_kernel<<<(NNZ + 511) / 512, 512>>>(idx, vals, NNZ);

    sort_kernel<<<nbuck, 1024>>>(M);

    {
        dim3 blk(32, 32);
        gather_kernel<<<(M + 31) / 32, blk>>>(out, bias, M, B);
    }
}

// round 11
// speedup vs baseline: 1.9295x; 1.9295x over previous
#include <cuda_runtime.h>

#define NMAX 131072
#define BV   32          // batch, inner stride of xT / acc

// Scratch: x transposed to (N, B) and accumulator (M, B).
__device__ float g_xT [(size_t)NMAX * BV];
__device__ float g_acc[(size_t)NMAX * BV];

// ---------------------------------------------------------------------------
// Zero the accumulator (float4 stores).
__global__ void zero_acc_kernel(int total4) {
    int i = blockIdx.x * blockDim.x + threadIdx.x;
    if (i < total4)
        reinterpret_cast<float4*>(g_acc)[i] = make_float4(0.f, 0.f, 0.f, 0.f);
}

// ---------------------------------------------------------------------------
// Transpose x (B, N) -> g_xT (N, B). 4 tiles of 32x32 per CTA for MLP.
__global__ __launch_bounds__(1024) void transpose_x_kernel(
        const float* __restrict__ x, int N, int B) {
    __shared__ float tile[4][32][33];
    int n0 = blockIdx.x * 128;
    int tx = threadIdx.x, ty = threadIdx.y;   // ty = batch on load
    #pragma unroll
    for (int t = 0; t < 4; t++) {
        int n = n0 + t * 32 + tx;
        if (ty < B && n < N)
            tile[t][ty][tx] = x[(size_t)ty * N + n];        // coalesced in n
    }
    __syncthreads();
    #pragma unroll
    for (int t = 0; t < 4; t++) {
        int nw = n0 + t * 32 + ty;
        if (tx < B && nw < N)
            g_xT[(size_t)nw * BV + tx] = tile[t][tx][ty];   // coalesced in b
    }
}

// ---------------------------------------------------------------------------
// Edge scatter: 8 threads per edge, one float4 (4 batches) per thread.
// Gather 128B row of xT[src], FMA by edge weight, vectorized red to acc[dst].
__global__ void edge_kernel(const int* __restrict__ idx,
                            const float* __restrict__ vals, int nnz) {
    int tid = blockIdx.x * blockDim.x + threadIdx.x;
    int e = tid >> 3;          // edge id
    int g = tid & 7;           // batch group (4 floats)
    if (e >= nnz) return;

    int   src = __ldg(idx + e);
    int   dst = __ldg(idx + nnz + e);
    float v   = __ldg(vals + e);

    const float4* xp = reinterpret_cast<const float4*>(g_xT + (size_t)src * BV) + g;
    float4 xv = __ldg(xp);

    float* ap = g_acc + (size_t)dst * BV + g * 4;
    asm volatile("red.global.add.v4.f32 [%0], {%1, %2, %3, %4};"
                 :: "l"(ap), "f"(xv.x * v), "f"(xv.y * v),
                    "f"(xv.z * v), "f"(xv.w * v)
                 : "memory");
}

// ---------------------------------------------------------------------------
// Transpose acc (M, B) -> out (B, M) + bias. 4 tiles of 32x32 per CTA.
__global__ __launch_bounds__(1024) void write_out_kernel(
        float* __restrict__ out, const float* __restrict__ bias, int M, int B) {
    __shared__ float tile[4][32][33];
    int m0 = blockIdx.x * 128;
    int tx = threadIdx.x, ty = threadIdx.y;
    #pragma unroll
    for (int t = 0; t < 4; t++) {
        int m = m0 + t * 32 + ty;
        if (m < M && tx < B)
            tile[t][ty][tx] = g_acc[(size_t)m * BV + tx];   // coalesced in b
    }
    __syncthreads();
    #pragma unroll
    for (int t = 0; t < 4; t++) {
        int mo = m0 + t * 32 + tx;
        if (mo < M && ty < B)
            out[(size_t)ty * M + mo] = tile[t][tx][ty] + __ldg(bias + mo);
    }
}

// ---------------------------------------------------------------------------
extern "C" void kernel_launch(void* const* d_in, const int* in_sizes, int n_in,
                              void* d_out, int out_size) {
    const float* x    = (const float*)d_in[0];   // (B, N, 1)
    const int*   idx  = (const int*)  d_in[1];   // (2, NNZ): row0=src, row1=dst
    const float* vals = (const float*)d_in[2];   // (NNZ,)
    const float* bias = (const float*)d_in[3];   // (M, 1)
    float*       out  = (float*)d_out;           // (B, M, 1)

    int M   = in_sizes[3];
    int NNZ = in_sizes[1] / 2;
    int B   = out_size / M;
    int N   = in_sizes[0] / B;

    {   // 1) zero accumulator
        int total4 = (M * B) / 4;
        zero_acc_kernel<<<(total4 + 255) / 256, 256>>>(total4);
    }
    {   // 2) transpose x -> xT (N, B)
        dim3 blk(32, 32);
        transpose_x_kernel<<<(N + 127) / 128, blk>>>(x, N, B);
    }
    {   // 3) edge scatter with vectorized global reductions
        long long threads = (long long)NNZ * 8;
        int blocks = (int)((threads + 255) / 256);
        edge_kernel<<<blocks, 256>>>(idx, vals, NNZ);
    }
    {   // 4) transpose acc -> out, add bias
        dim3 blk(32, 32);
        write_out_kernel<<<(M + 127) / 128, blk>>>(out, bias, M, B);
    }
}